// round 9
// baseline (speedup 1.0000x reference)
#include <cuda_runtime.h>
#include <math.h>

#define NN 8192
#define DINV_C 0.011048543456039806f   /* (float)(1/sqrt(8192)) */
#define MAXD 256
#define RPB 56          /* rows per block in k_pass: 14 warps x 4 */
#define GRIDP 147       /* ceil(8192/56) = 147 <= 148 SMs -> single wave */
#define PFDIST 8        /* L2 prefetch distance in 128-float segments */

static __device__ float g_s1T[10 * NN];   // XW1 transposed [k][j], UNSCALED
static __device__ float g_U1[NN * 10];    // adj @ XW1
static __device__ float g_minrow[NN];
static __device__ float g_dinv[NN];
static __device__ int   g_defect[MAXD];
static __device__ int   g_ndef;
static __device__ float g_s2T[6 * NN];    // s2 transposed [m][j], col 5 = zero pad
static __device__ float g_U2[NN * 6];
static __device__ float g_part[64 * 5];

// ---------------------------------------------------------------------------
// packed fp32x2 FMA (FFMA2) — only reachable via PTX on sm_103a
// ---------------------------------------------------------------------------
__device__ __forceinline__ unsigned long long ffma2(unsigned long long a,
                                                    unsigned long long b,
                                                    unsigned long long c) {
    unsigned long long d;
    asm("fma.rn.f32x2 %0, %1, %2, %3;" : "=l"(d) : "l"(a), "l"(b), "l"(c));
    return d;
}
union U64F2 { unsigned long long u; float2 f; };
__device__ __forceinline__ float2 u2f(unsigned long long u) { U64F2 t; t.u = u; return t.f; }

__device__ __forceinline__ void pf_l2(const float* p) {
    asm volatile("prefetch.global.L2 [%0];" :: "l"(p));
}

// ---------------------------------------------------------------------------
// K1: s1T[k][i] = (x @ W1)[i][k].  4 lanes per row (q = lane quarter).
// ---------------------------------------------------------------------------
__global__ void __launch_bounds__(256) k_xw1(const float* __restrict__ x,
                                             const float* __restrict__ W1) {
    __shared__ float w[128 * 10];
    int tid = threadIdx.x;
    for (int t = tid; t < 128 * 10; t += 256) w[t] = W1[t];
    __syncthreads();
    int g = blockIdx.x * 256 + tid;          // 0..32767
    int i = g >> 2, q = g & 3;               // row, quarter
    float acc[10];
#pragma unroll
    for (int k = 0; k < 10; k++) acc[k] = 0.f;
    const float4* xr = (const float4*)(x + (size_t)i * 128 + q * 32);
#pragma unroll
    for (int c4 = 0; c4 < 8; c4++) {
        float4 xv = xr[c4];
        int cb = (q * 32 + c4 * 4) * 10;
#pragma unroll
        for (int k = 0; k < 10; k++) {
            acc[k] += xv.x * w[cb + k];
            acc[k] += xv.y * w[cb + 10 + k];
            acc[k] += xv.z * w[cb + 20 + k];
            acc[k] += xv.w * w[cb + 30 + k];
        }
    }
#pragma unroll
    for (int k = 0; k < 10; k++) {
        acc[k] += __shfl_xor_sync(0xffffffffu, acc[k], 1);
        acc[k] += __shfl_xor_sync(0xffffffffu, acc[k], 2);
    }
    if (q == 0)
#pragma unroll
        for (int k = 0; k < 10; k++) g_s1T[k * NN + i] = acc[k];
}

// ---------------------------------------------------------------------------
// Main pass: U[i][k] = sum_j adj[i][j] * sT[k][j]   (+ per-row min tracking)
// 448 thr (14 warps) x 4 rows/warp = 56 rows/block, grid 147 -> ONE WAVE.
// DEPTH-deep register prefetch (1 for KT=10, 2 for KT=6) covers L2-hit
// latency; prefetch.global.L2 at PFDIST segments covers DRAM->L2, reg-free.
// ---------------------------------------------------------------------------
template <int KT, int JTILE, bool TRACK, int PASS, int DEPTH>
__global__ void __launch_bounds__(448, 1) k_pass(const float* __restrict__ adj) {
    const float* __restrict__ sT = (PASS == 1) ? g_s1T : g_s2T;
    float* __restrict__ U        = (PASS == 1) ? g_U1  : g_U2;
    extern __shared__ __align__(16) float tile[];   // KT * JTILE floats

    const int tid  = threadIdx.x;
    const int warp = tid >> 5, lane = tid & 31;
    const int row0 = blockIdx.x * RPB + warp * 4;
    const int row0c = (row0 > NN - 4) ? (NN - 4) : row0;   // clamp: dup reads, no writes
    const bool ok = (row0 < NN);                            // whole-warp validity
    const float* __restrict__ rp = adj + (size_t)row0c * NN;

    unsigned long long acc[4][KT];
#pragma unroll
    for (int r = 0; r < 4; r++)
#pragma unroll
        for (int k = 0; k < KT; k++) acc[r][k] = 0ull;

    float rmin[4];
#pragma unroll
    for (int r = 0; r < 4; r++) rmin[r] = 3.4e38f;

    constexpr int NSEG = NN / 128;
    constexpr int IPT  = JTILE / 128;
    constexpr int NT   = NN / JTILE;

    // load tile 0
    for (int idx = tid; idx < KT * (JTILE / 4); idx += 448) {
        int k = idx / (JTILE / 4), q = idx % (JTILE / 4);
        ((float4*)tile)[idx] = ((const float4*)(sT + (size_t)k * NN))[q];
    }
    __syncthreads();

    // warm L2 for first PFDIST segments + DEPTH-deep register prefetch
    longlong2 a0[4], a1[4];
    {
        const int g0 = lane * 4;
#pragma unroll
        for (int r = 0; r < 4; r++)
            a0[r] = *(const longlong2*)(rp + (size_t)r * NN + g0);
        if (DEPTH == 2) {
#pragma unroll
            for (int r = 0; r < 4; r++)
                a1[r] = *(const longlong2*)(rp + (size_t)r * NN + 128 + g0);
        }
#pragma unroll
        for (int s = 1; s <= PFDIST; s++)
#pragma unroll
            for (int r = 0; r < 4; r++)
                pf_l2(rp + (size_t)r * NN + s * 128 + lane * 4);
    }

    for (int tI = 0; tI < NT; tI++) {
        if (tI > 0) {
            __syncthreads();
            for (int idx = tid; idx < KT * (JTILE / 4); idx += 448) {
                int k = idx / (JTILE / 4), q = idx % (JTILE / 4);
                ((float4*)tile)[idx] =
                    ((const float4*)(sT + (size_t)k * NN + (size_t)tI * JTILE))[q];
            }
            __syncthreads();
        }
#pragma unroll 2
        for (int it = 0; it < IPT; it++) {
            const int seg = tI * IPT + it;
            // L2 prefetch PFDIST+1 ahead (wraps harmlessly at the end)
            {
                int sp = seg + PFDIST + 1;
                if (sp >= NSEG) sp -= NSEG;
                const int gpf = sp * 128 + lane * 4;
#pragma unroll
                for (int r = 0; r < 4; r++)
                    pf_l2(rp + (size_t)r * NN + gpf);
            }
            // register prefetch of segment seg+DEPTH (should be L2-resident)
            longlong2 an[4];
            {
                const int sn = seg + DEPTH;
                const int gp = (sn < NSEG) ? sn * 128 + lane * 4 : lane * 4;
#pragma unroll
                for (int r = 0; r < 4; r++)
                    an[r] = *(const longlong2*)(rp + (size_t)r * NN + gp);
            }
            if (TRACK) {
#pragma unroll
                for (int r = 0; r < 4; r++) {
                    float2 lo = u2f((unsigned long long)a0[r].x);
                    float2 hi = u2f((unsigned long long)a0[r].y);
                    rmin[r] = fminf(rmin[r], fminf(fminf(lo.x, lo.y), fminf(hi.x, hi.y)));
                }
            }
            const int js = it * 128 + lane * 4;
#pragma unroll
            for (int k = 0; k < KT; k++) {
                longlong2 sv = *(const longlong2*)&tile[k * JTILE + js];
#pragma unroll
                for (int r = 0; r < 4; r++) {
                    acc[r][k] = ffma2((unsigned long long)a0[r].x, (unsigned long long)sv.x, acc[r][k]);
                    acc[r][k] = ffma2((unsigned long long)a0[r].y, (unsigned long long)sv.y, acc[r][k]);
                }
            }
            if (DEPTH == 2) {
#pragma unroll
                for (int r = 0; r < 4; r++) { a0[r] = a1[r]; a1[r] = an[r]; }
            } else {
#pragma unroll
                for (int r = 0; r < 4; r++) a0[r] = an[r];
            }
        }
    }

    // lane reduction + writes
#pragma unroll
    for (int r = 0; r < 4; r++) {
#pragma unroll
        for (int k = 0; k < KT; k++) {
            float2 v = u2f(acc[r][k]);
            float s = v.x + v.y;
#pragma unroll
            for (int o = 16; o > 0; o >>= 1) s += __shfl_xor_sync(0xffffffffu, s, o);
            if (lane == 0 && ok) U[(size_t)(row0c + r) * KT + k] = s;
        }
        if (TRACK) {
            float m = rmin[r];
#pragma unroll
            for (int o = 16; o > 0; o >>= 1) m = fminf(m, __shfl_xor_sync(0xffffffffu, m, o));
            if (lane == 0 && ok) g_minrow[row0c + r] = m;
        }
    }
}

// ---------------------------------------------------------------------------
// K3: scan minrow -> default dinv + deterministic defect-list compaction
// ---------------------------------------------------------------------------
__global__ void __launch_bounds__(1024) k_scan() {
    __shared__ int warp_cnt[32];
    __shared__ int warp_off[32];
    __shared__ int base;
    int tid = threadIdx.x, w = tid >> 5, lane = tid & 31;
    if (tid == 0) base = 0;
    __syncthreads();
    for (int chunk = 0; chunk < NN; chunk += 1024) {
        int i = chunk + tid;
        bool f = (g_minrow[i] <= 0.0f);
        g_dinv[i] = DINV_C;
        unsigned m = __ballot_sync(0xffffffffu, f);
        if (lane == 0) warp_cnt[w] = __popc(m);
        __syncthreads();
        if (tid == 0) {
            int o = base;
            for (int q = 0; q < 32; q++) { warp_off[q] = o; o += warp_cnt[q]; }
            base = o;
        }
        __syncthreads();
        if (f) {
            int pos = warp_off[w] + __popc(m & ((1u << lane) - 1u));
            if (pos < MAXD) g_defect[pos] = i;
        }
        __syncthreads();
    }
    if (tid == 0) g_ndef = (base > MAXD) ? MAXD : base;
}

// ---------------------------------------------------------------------------
// K4: exact deg recount for defect rows only
// ---------------------------------------------------------------------------
__global__ void __launch_bounds__(1024) k_recount(const float* __restrict__ adj) {
    __shared__ int red[1024];
    int nd = g_ndef;
    for (int d = blockIdx.x; d < nd; d += gridDim.x) {
        int j = g_defect[d];
        int cnt = 0;
        for (int t = threadIdx.x; t < NN; t += 1024)
            cnt += (adj[(size_t)j * NN + t] > 0.0f) ? 1 : 0;
        red[threadIdx.x] = cnt;
        __syncthreads();
        for (int s = 512; s > 0; s >>= 1) {
            if (threadIdx.x < s) red[threadIdx.x] += red[threadIdx.x + s];
            __syncthreads();
        }
        if (threadIdx.x == 0)
            g_dinv[j] = (red[0] > 0) ? (1.0f / sqrtf((float)red[0])) : __int_as_float(0x7f800000);
        __syncthreads();
    }
}

// ---------------------------------------------------------------------------
// K5: defect correction + h = relu(gcn1) + s2T = (h@W2)*dinv (transposed)
// ---------------------------------------------------------------------------
__global__ void __launch_bounds__(128) k_h_s2(const float* __restrict__ adj,
                                              const float* __restrict__ b1,
                                              const float* __restrict__ W2) {
    __shared__ float sb1[10], sW2[50];
    __shared__ int   sjd[MAXD];
    __shared__ float sdv[MAXD];
    __shared__ float sxw[MAXD * 10];
    __shared__ int   snd;
    int tid = threadIdx.x;
    if (tid < 10) sb1[tid] = b1[tid];
    if (tid < 50) sW2[tid] = W2[tid];
    if (tid == 0) { int n = g_ndef; snd = (n > MAXD) ? MAXD : n; }
    __syncthreads();
    int nd = snd;
    for (int d = tid; d < nd; d += blockDim.x) {
        int j = g_defect[d];
        sjd[d] = j;
        sdv[d] = g_dinv[j] - DINV_C;
        for (int k = 0; k < 10; k++) sxw[d * 10 + k] = g_s1T[k * NN + j];
    }
    __syncthreads();

    int i = blockIdx.x * blockDim.x + tid;
    float di = g_dinv[i];
    float u[10];
#pragma unroll
    for (int k = 0; k < 10; k++) u[k] = DINV_C * g_U1[(size_t)i * 10 + k];
    for (int d = 0; d < nd; d++) {
        float a = adj[(size_t)i * NN + sjd[d]] * sdv[d];
#pragma unroll
        for (int k = 0; k < 10; k++) u[k] += a * sxw[d * 10 + k];
    }
    float h[10];
#pragma unroll
    for (int k = 0; k < 10; k++) {
        float self = g_s1T[k * NN + i] * di;
        float v = di * (u[k] + self) + sb1[k];
        h[k] = v > 0.f ? v : 0.f;
    }
#pragma unroll
    for (int m = 0; m < 5; m++) {
        float s = 0.f;
#pragma unroll
        for (int k = 0; k < 10; k++) s += h[k] * sW2[k * 5 + m];
        g_s2T[m * NN + i] = s * di;
    }
    g_s2T[5 * NN + i] = 0.f;   // zero pad column (KT=6 in pass 2)
}

// ---------------------------------------------------------------------------
// K6a: partial column sums of dinv*(U2 + s2T) over i, 64 blocks
// ---------------------------------------------------------------------------
__global__ void __launch_bounds__(128) k_final_a() {
    __shared__ float wsum[4][5];
    int tid = threadIdx.x, lane = tid & 31, w = tid >> 5;
    int i = blockIdx.x * 128 + tid;
    float di = g_dinv[i];
    float s[5];
#pragma unroll
    for (int m = 0; m < 5; m++)
        s[m] = di * (g_U2[(size_t)i * 6 + m] + g_s2T[m * NN + i]);
#pragma unroll
    for (int m = 0; m < 5; m++) {
        float v = s[m];
#pragma unroll
        for (int o = 16; o > 0; o >>= 1) v += __shfl_xor_sync(0xffffffffu, v, o);
        if (lane == 0) wsum[w][m] = v;
    }
    __syncthreads();
    if (tid < 5) {
        float t = wsum[0][tid] + wsum[1][tid] + wsum[2][tid] + wsum[3][tid];
        g_part[blockIdx.x * 5 + tid] = t;
    }
}

// ---------------------------------------------------------------------------
// K6b: finish mean + tiny MLP head, writes 7 outputs
// ---------------------------------------------------------------------------
__global__ void __launch_bounds__(32) k_final_b(const float* __restrict__ b2,
                                                const float* __restrict__ fc1W,
                                                const float* __restrict__ fc1b,
                                                const float* __restrict__ fcW,
                                                const float* __restrict__ fcb,
                                                float* __restrict__ out, int out_size) {
    if (threadIdx.x == 0) {
        float z[5], z2[5];
        for (int m = 0; m < 5; m++) {
            float t = 0.f;
            for (int q = 0; q < 64; q++) t += g_part[q * 5 + m];
            t = t * (1.0f / (float)NN) + b2[m];
            z[m] = t > 0.f ? t : 0.f;
        }
        for (int j = 0; j < 5; j++) {
            float a = fc1b[j];
            for (int m = 0; m < 5; m++) a += z[m] * fc1W[m * 5 + j];
            z2[j] = a > 0.f ? a : 0.f;
        }
        float y[2];
        for (int t2 = 0; t2 < 2; t2++) {
            float a = fcb[t2];
            for (int j = 0; j < 5; j++) a += z2[j] * fcW[j * 2 + t2];
            y[t2] = 1.0f / (1.0f + expf(-a));
        }
        for (int m = 0; m < 5; m++) if (m < out_size) out[m] = z[m];
        if (out_size > 5) out[5] = y[0];
        if (out_size > 6) out[6] = y[1];
    }
}

// ---------------------------------------------------------------------------
extern "C" void kernel_launch(void* const* d_in, const int* in_sizes, int n_in,
                              void* d_out, int out_size) {
    const float* x    = (const float*)d_in[0];
    const float* adj  = (const float*)d_in[1];
    const float* W1   = (const float*)d_in[2];
    const float* b1   = (const float*)d_in[3];
    const float* W2   = (const float*)d_in[4];
    const float* b2   = (const float*)d_in[5];
    const float* fc1W = (const float*)d_in[6];
    const float* fc1b = (const float*)d_in[7];
    const float* fcW  = (const float*)d_in[8];
    const float* fcb  = (const float*)d_in[9];
    float* out = (float*)d_out;

    // pass1: KT=10, JTILE=4096 -> 160KB smem (one reload), DEPTH=1;
    // pass2: KT=6, whole sT -> 192KB smem (zero reloads), DEPTH=2
    const int smem1 = 10 * 4096 * 4;
    const int smem2 = 6 * 8192 * 4;
    cudaFuncSetAttribute(k_pass<10, 4096, true, 1, 1>,
                         cudaFuncAttributeMaxDynamicSharedMemorySize, smem1);
    cudaFuncSetAttribute(k_pass<6, 8192, false, 2, 2>,
                         cudaFuncAttributeMaxDynamicSharedMemorySize, smem2);

    k_xw1<<<128, 256>>>(x, W1);
    k_pass<10, 4096, true, 1, 1><<<GRIDP, 448, smem1>>>(adj);
    k_scan<<<1, 1024>>>();
    k_recount<<<16, 1024>>>(adj);
    k_h_s2<<<64, 128>>>(adj, b1, W2);
    k_pass<6, 8192, false, 2, 2><<<GRIDP, 448, smem2>>>(adj);
    k_final_a<<<64, 128>>>();
    k_final_b<<<1, 32>>>(b2, fc1W, fc1b, fcW, fcb, out, out_size);
}

// round 10
// speedup vs baseline: 1.0922x; 1.0922x over previous
#include <cuda_runtime.h>
#include <math.h>

#define NN 8192
#define DINV_C 0.011048543456039806f   /* (float)(1/sqrt(8192)) */
#define MAXD 256
#define RPB 56          /* rows per block in k_pass: 14 warps x 4 */
#define GRIDP 147       /* ceil(8192/56) = 147 <= 148 SMs -> single wave */
#define PFDIST 4        /* L2 prefetch distance in 128-float segments */

static __device__ float g_s1T[10 * NN];   // XW1 transposed [k][j], UNSCALED
static __device__ float g_U1[NN * 10];    // adj @ XW1
static __device__ float g_minrow[NN];
static __device__ float g_dinv[NN];
static __device__ int   g_defect[MAXD];
static __device__ int   g_ndef;
static __device__ float g_s2T[6 * NN];    // s2 transposed [m][j], col 5 = zero pad
static __device__ float g_U2[NN * 6];
static __device__ float g_part[64 * 5];

// ---------------------------------------------------------------------------
// packed fp32x2 FMA (FFMA2) — only reachable via PTX on sm_103a
// ---------------------------------------------------------------------------
__device__ __forceinline__ unsigned long long ffma2(unsigned long long a,
                                                    unsigned long long b,
                                                    unsigned long long c) {
    unsigned long long d;
    asm("fma.rn.f32x2 %0, %1, %2, %3;" : "=l"(d) : "l"(a), "l"(b), "l"(c));
    return d;
}
union U64F2 { unsigned long long u; float2 f; };
__device__ __forceinline__ float2 u2f(unsigned long long u) { U64F2 t; t.u = u; return t.f; }

__device__ __forceinline__ void pf_l2(const float* p) {
    asm volatile("prefetch.global.L2 [%0];" :: "l"(p));
}

// ---------------------------------------------------------------------------
// K1: s1T[k][i] = (x @ W1)[i][k].  4 lanes per row (q = lane quarter).
// ---------------------------------------------------------------------------
__global__ void __launch_bounds__(256) k_xw1(const float* __restrict__ x,
                                             const float* __restrict__ W1) {
    __shared__ float w[128 * 10];
    int tid = threadIdx.x;
    for (int t = tid; t < 128 * 10; t += 256) w[t] = W1[t];
    __syncthreads();
    int g = blockIdx.x * 256 + tid;          // 0..32767
    int i = g >> 2, q = g & 3;               // row, quarter
    float acc[10];
#pragma unroll
    for (int k = 0; k < 10; k++) acc[k] = 0.f;
    const float4* xr = (const float4*)(x + (size_t)i * 128 + q * 32);
#pragma unroll
    for (int c4 = 0; c4 < 8; c4++) {
        float4 xv = xr[c4];
        int cb = (q * 32 + c4 * 4) * 10;
#pragma unroll
        for (int k = 0; k < 10; k++) {
            acc[k] += xv.x * w[cb + k];
            acc[k] += xv.y * w[cb + 10 + k];
            acc[k] += xv.z * w[cb + 20 + k];
            acc[k] += xv.w * w[cb + 30 + k];
        }
    }
#pragma unroll
    for (int k = 0; k < 10; k++) {
        acc[k] += __shfl_xor_sync(0xffffffffu, acc[k], 1);
        acc[k] += __shfl_xor_sync(0xffffffffu, acc[k], 2);
    }
    if (q == 0)
#pragma unroll
        for (int k = 0; k < 10; k++) g_s1T[k * NN + i] = acc[k];
}

// ---------------------------------------------------------------------------
// Main pass: U[i][k] = sum_j adj[i][j] * sT[k][j]   (+ per-row min tracking)
// 448 thr (14 warps) x 4 rows/warp = 56 rows/block, grid 147 -> ONE WAVE.
// 1-deep register prefetch covers L2-hit latency; DEDUPED prefetch.global.L2
// (1 request per 128B line: lanes 0-15 cover 4 rows x 4 lines) covers DRAM->L2.
// ---------------------------------------------------------------------------
template <int KT, int JTILE, bool TRACK, int PASS>
__global__ void __launch_bounds__(448, 1) k_pass(const float* __restrict__ adj) {
    const float* __restrict__ sT = (PASS == 1) ? g_s1T : g_s2T;
    float* __restrict__ U        = (PASS == 1) ? g_U1  : g_U2;
    extern __shared__ __align__(16) float tile[];   // KT * JTILE floats

    const int tid  = threadIdx.x;
    const int warp = tid >> 5, lane = tid & 31;
    const int row0 = blockIdx.x * RPB + warp * 4;
    const int row0c = (row0 > NN - 4) ? (NN - 4) : row0;   // clamp: dup reads, no writes
    const bool ok = (row0 < NN);                            // whole-warp validity
    const float* __restrict__ rp = adj + (size_t)row0c * NN;

    // deduped prefetch address component: lanes 0-15, row=lane>>2, line=lane&3
    const bool pfl = (lane < 16);
    const size_t pfoff = (size_t)(lane >> 2) * NN + (lane & 3) * 32;

    unsigned long long acc[4][KT];
#pragma unroll
    for (int r = 0; r < 4; r++)
#pragma unroll
        for (int k = 0; k < KT; k++) acc[r][k] = 0ull;

    float rmin[4];
#pragma unroll
    for (int r = 0; r < 4; r++) rmin[r] = 3.4e38f;

    constexpr int NSEG = NN / 128;
    constexpr int IPT  = JTILE / 128;
    constexpr int NT   = NN / JTILE;

    // load tile 0
    for (int idx = tid; idx < KT * (JTILE / 4); idx += 448) {
        int k = idx / (JTILE / 4), q = idx % (JTILE / 4);
        ((float4*)tile)[idx] = ((const float4*)(sT + (size_t)k * NN))[q];
    }
    __syncthreads();

    // warm L2 for first PFDIST segments + 1-deep register prefetch
    longlong2 a[4];
    {
        const int g0 = lane * 4;
#pragma unroll
        for (int r = 0; r < 4; r++)
            a[r] = *(const longlong2*)(rp + (size_t)r * NN + g0);
        if (pfl) {
#pragma unroll
            for (int s = 1; s <= PFDIST; s++)
                pf_l2(rp + pfoff + s * 128);
        }
    }

    for (int tI = 0; tI < NT; tI++) {
        if (tI > 0) {
            __syncthreads();
            for (int idx = tid; idx < KT * (JTILE / 4); idx += 448) {
                int k = idx / (JTILE / 4), q = idx % (JTILE / 4);
                ((float4*)tile)[idx] =
                    ((const float4*)(sT + (size_t)k * NN + (size_t)tI * JTILE))[q];
            }
            __syncthreads();
        }
#pragma unroll 2
        for (int it = 0; it < IPT; it++) {
            const int seg = tI * IPT + it;
            // deduped L2 prefetch PFDIST+1 ahead (wraps harmlessly at the end)
            {
                int sp = seg + PFDIST + 1;
                if (sp >= NSEG) sp -= NSEG;
                if (pfl) pf_l2(rp + pfoff + sp * 128);
            }
            // register prefetch of next segment (should be L2-resident)
            longlong2 an[4];
            {
                const int gp = (seg + 1 < NSEG) ? (seg + 1) * 128 + lane * 4 : lane * 4;
#pragma unroll
                for (int r = 0; r < 4; r++)
                    an[r] = *(const longlong2*)(rp + (size_t)r * NN + gp);
            }
            if (TRACK) {
#pragma unroll
                for (int r = 0; r < 4; r++) {
                    float2 lo = u2f((unsigned long long)a[r].x);
                    float2 hi = u2f((unsigned long long)a[r].y);
                    rmin[r] = fminf(rmin[r], fminf(fminf(lo.x, lo.y), fminf(hi.x, hi.y)));
                }
            }
            const int js = it * 128 + lane * 4;
#pragma unroll
            for (int k = 0; k < KT; k++) {
                longlong2 sv = *(const longlong2*)&tile[k * JTILE + js];
#pragma unroll
                for (int r = 0; r < 4; r++) {
                    acc[r][k] = ffma2((unsigned long long)a[r].x, (unsigned long long)sv.x, acc[r][k]);
                    acc[r][k] = ffma2((unsigned long long)a[r].y, (unsigned long long)sv.y, acc[r][k]);
                }
            }
#pragma unroll
            for (int r = 0; r < 4; r++) a[r] = an[r];
        }
    }

    // lane reduction + writes
#pragma unroll
    for (int r = 0; r < 4; r++) {
#pragma unroll
        for (int k = 0; k < KT; k++) {
            float2 v = u2f(acc[r][k]);
            float s = v.x + v.y;
#pragma unroll
            for (int o = 16; o > 0; o >>= 1) s += __shfl_xor_sync(0xffffffffu, s, o);
            if (lane == 0 && ok) U[(size_t)(row0c + r) * KT + k] = s;
        }
        if (TRACK) {
            float m = rmin[r];
#pragma unroll
            for (int o = 16; o > 0; o >>= 1) m = fminf(m, __shfl_xor_sync(0xffffffffu, m, o));
            if (lane == 0 && ok) g_minrow[row0c + r] = m;
        }
    }
}

// ---------------------------------------------------------------------------
// K3: scan minrow -> default dinv + deterministic defect-list compaction
// ---------------------------------------------------------------------------
__global__ void __launch_bounds__(1024) k_scan() {
    __shared__ int warp_cnt[32];
    __shared__ int warp_off[32];
    __shared__ int base;
    int tid = threadIdx.x, w = tid >> 5, lane = tid & 31;
    if (tid == 0) base = 0;
    __syncthreads();
    for (int chunk = 0; chunk < NN; chunk += 1024) {
        int i = chunk + tid;
        bool f = (g_minrow[i] <= 0.0f);
        g_dinv[i] = DINV_C;
        unsigned m = __ballot_sync(0xffffffffu, f);
        if (lane == 0) warp_cnt[w] = __popc(m);
        __syncthreads();
        if (tid == 0) {
            int o = base;
            for (int q = 0; q < 32; q++) { warp_off[q] = o; o += warp_cnt[q]; }
            base = o;
        }
        __syncthreads();
        if (f) {
            int pos = warp_off[w] + __popc(m & ((1u << lane) - 1u));
            if (pos < MAXD) g_defect[pos] = i;
        }
        __syncthreads();
    }
    if (tid == 0) g_ndef = (base > MAXD) ? MAXD : base;
}

// ---------------------------------------------------------------------------
// K4: exact deg recount for defect rows only
// ---------------------------------------------------------------------------
__global__ void __launch_bounds__(1024) k_recount(const float* __restrict__ adj) {
    __shared__ int red[1024];
    int nd = g_ndef;
    for (int d = blockIdx.x; d < nd; d += gridDim.x) {
        int j = g_defect[d];
        int cnt = 0;
        for (int t = threadIdx.x; t < NN; t += 1024)
            cnt += (adj[(size_t)j * NN + t] > 0.0f) ? 1 : 0;
        red[threadIdx.x] = cnt;
        __syncthreads();
        for (int s = 512; s > 0; s >>= 1) {
            if (threadIdx.x < s) red[threadIdx.x] += red[threadIdx.x + s];
            __syncthreads();
        }
        if (threadIdx.x == 0)
            g_dinv[j] = (red[0] > 0) ? (1.0f / sqrtf((float)red[0])) : __int_as_float(0x7f800000);
        __syncthreads();
    }
}

// ---------------------------------------------------------------------------
// K5: defect correction + h = relu(gcn1) + s2T = (h@W2)*dinv (transposed)
// ---------------------------------------------------------------------------
__global__ void __launch_bounds__(128) k_h_s2(const float* __restrict__ adj,
                                              const float* __restrict__ b1,
                                              const float* __restrict__ W2) {
    __shared__ float sb1[10], sW2[50];
    __shared__ int   sjd[MAXD];
    __shared__ float sdv[MAXD];
    __shared__ float sxw[MAXD * 10];
    __shared__ int   snd;
    int tid = threadIdx.x;
    if (tid < 10) sb1[tid] = b1[tid];
    if (tid < 50) sW2[tid] = W2[tid];
    if (tid == 0) { int n = g_ndef; snd = (n > MAXD) ? MAXD : n; }
    __syncthreads();
    int nd = snd;
    for (int d = tid; d < nd; d += blockDim.x) {
        int j = g_defect[d];
        sjd[d] = j;
        sdv[d] = g_dinv[j] - DINV_C;
        for (int k = 0; k < 10; k++) sxw[d * 10 + k] = g_s1T[k * NN + j];
    }
    __syncthreads();

    int i = blockIdx.x * blockDim.x + tid;
    float di = g_dinv[i];
    float u[10];
#pragma unroll
    for (int k = 0; k < 10; k++) u[k] = DINV_C * g_U1[(size_t)i * 10 + k];
    for (int d = 0; d < nd; d++) {
        float a = adj[(size_t)i * NN + sjd[d]] * sdv[d];
#pragma unroll
        for (int k = 0; k < 10; k++) u[k] += a * sxw[d * 10 + k];
    }
    float h[10];
#pragma unroll
    for (int k = 0; k < 10; k++) {
        float self = g_s1T[k * NN + i] * di;
        float v = di * (u[k] + self) + sb1[k];
        h[k] = v > 0.f ? v : 0.f;
    }
#pragma unroll
    for (int m = 0; m < 5; m++) {
        float s = 0.f;
#pragma unroll
        for (int k = 0; k < 10; k++) s += h[k] * sW2[k * 5 + m];
        g_s2T[m * NN + i] = s * di;
    }
    g_s2T[5 * NN + i] = 0.f;   // zero pad column (KT=6 in pass 2)
}

// ---------------------------------------------------------------------------
// K6a: partial column sums of dinv*(U2 + s2T) over i, 64 blocks
// ---------------------------------------------------------------------------
__global__ void __launch_bounds__(128) k_final_a() {
    __shared__ float wsum[4][5];
    int tid = threadIdx.x, lane = tid & 31, w = tid >> 5;
    int i = blockIdx.x * 128 + tid;
    float di = g_dinv[i];
    float s[5];
#pragma unroll
    for (int m = 0; m < 5; m++)
        s[m] = di * (g_U2[(size_t)i * 6 + m] + g_s2T[m * NN + i]);
#pragma unroll
    for (int m = 0; m < 5; m++) {
        float v = s[m];
#pragma unroll
        for (int o = 16; o > 0; o >>= 1) v += __shfl_xor_sync(0xffffffffu, v, o);
        if (lane == 0) wsum[w][m] = v;
    }
    __syncthreads();
    if (tid < 5) {
        float t = wsum[0][tid] + wsum[1][tid] + wsum[2][tid] + wsum[3][tid];
        g_part[blockIdx.x * 5 + tid] = t;
    }
}

// ---------------------------------------------------------------------------
// K6b: finish mean + tiny MLP head, writes 7 outputs
// ---------------------------------------------------------------------------
__global__ void __launch_bounds__(32) k_final_b(const float* __restrict__ b2,
                                                const float* __restrict__ fc1W,
                                                const float* __restrict__ fc1b,
                                                const float* __restrict__ fcW,
                                                const float* __restrict__ fcb,
                                                float* __restrict__ out, int out_size) {
    if (threadIdx.x == 0) {
        float z[5], z2[5];
        for (int m = 0; m < 5; m++) {
            float t = 0.f;
            for (int q = 0; q < 64; q++) t += g_part[q * 5 + m];
            t = t * (1.0f / (float)NN) + b2[m];
            z[m] = t > 0.f ? t : 0.f;
        }
        for (int j = 0; j < 5; j++) {
            float a = fc1b[j];
            for (int m = 0; m < 5; m++) a += z[m] * fc1W[m * 5 + j];
            z2[j] = a > 0.f ? a : 0.f;
        }
        float y[2];
        for (int t2 = 0; t2 < 2; t2++) {
            float a = fcb[t2];
            for (int j = 0; j < 5; j++) a += z2[j] * fcW[j * 2 + t2];
            y[t2] = 1.0f / (1.0f + expf(-a));
        }
        for (int m = 0; m < 5; m++) if (m < out_size) out[m] = z[m];
        if (out_size > 5) out[5] = y[0];
        if (out_size > 6) out[6] = y[1];
    }
}

// ---------------------------------------------------------------------------
extern "C" void kernel_launch(void* const* d_in, const int* in_sizes, int n_in,
                              void* d_out, int out_size) {
    const float* x    = (const float*)d_in[0];
    const float* adj  = (const float*)d_in[1];
    const float* W1   = (const float*)d_in[2];
    const float* b1   = (const float*)d_in[3];
    const float* W2   = (const float*)d_in[4];
    const float* b2   = (const float*)d_in[5];
    const float* fc1W = (const float*)d_in[6];
    const float* fc1b = (const float*)d_in[7];
    const float* fcW  = (const float*)d_in[8];
    const float* fcb  = (const float*)d_in[9];
    float* out = (float*)d_out;

    // pass1: KT=10, JTILE=4096 -> 160KB smem (one reload);
    // pass2: KT=6, whole sT -> 192KB smem (zero reloads)
    const int smem1 = 10 * 4096 * 4;
    const int smem2 = 6 * 8192 * 4;
    cudaFuncSetAttribute(k_pass<10, 4096, true, 1>,
                         cudaFuncAttributeMaxDynamicSharedMemorySize, smem1);
    cudaFuncSetAttribute(k_pass<6, 8192, false, 2>,
                         cudaFuncAttributeMaxDynamicSharedMemorySize, smem2);

    k_xw1<<<128, 256>>>(x, W1);
    k_pass<10, 4096, true, 1><<<GRIDP, 448, smem1>>>(adj);
    k_scan<<<1, 1024>>>();
    k_recount<<<16, 1024>>>(adj);
    k_h_s2<<<64, 128>>>(adj, b1, W2);
    k_pass<6, 8192, false, 2><<<GRIDP, 448, smem2>>>(adj);
    k_final_a<<<64, 128>>>();
    k_final_b<<<1, 32>>>(b2, fc1W, fc1b, fcW, fcb, out, out_size);
}

// round 11
// speedup vs baseline: 1.1594x; 1.0615x over previous
#include <cuda_runtime.h>
#include <math.h>

#define NN 8192
#define DINV_C 0.011048543456039806f   /* (float)(1/sqrt(8192)) */
#define MAXD 256
#define RPB 56          /* rows per block in k_pass: 14 warps x 4 */
#define GRIDP 147       /* ceil(8192/56) = 147 <= 148 SMs -> single wave */

static __device__ float g_s1T[10 * NN];   // XW1 transposed [k][j], UNSCALED
static __device__ float g_U1[NN * 10];    // adj @ XW1
static __device__ float g_minrow[NN];
static __device__ float g_dinv[NN];
static __device__ int   g_defect[MAXD];
static __device__ int   g_ndef;
static __device__ float g_s2T[5 * NN];    // s2 transposed [m][j], exact
static __device__ float g_U2[NN * 5];
static __device__ float g_part[64 * 5];

// ---------------------------------------------------------------------------
// packed fp32x2 FMA (FFMA2) — only reachable via PTX on sm_103a
// ---------------------------------------------------------------------------
__device__ __forceinline__ unsigned long long ffma2(unsigned long long a,
                                                    unsigned long long b,
                                                    unsigned long long c) {
    unsigned long long d;
    asm("fma.rn.f32x2 %0, %1, %2, %3;" : "=l"(d) : "l"(a), "l"(b), "l"(c));
    return d;
}
union U64F2 { unsigned long long u; float2 f; };
__device__ __forceinline__ float2 u2f(unsigned long long u) { U64F2 t; t.u = u; return t.f; }

__device__ __forceinline__ void cp_async16(unsigned dst, const float* src) {
    asm volatile("cp.async.cg.shared.global [%0], [%1], 16;" :: "r"(dst), "l"(src));
}

// ---------------------------------------------------------------------------
// K1: s1T[k][i] = (x @ W1)[i][k].  4 lanes per row (q = lane quarter).
// ---------------------------------------------------------------------------
__global__ void __launch_bounds__(256) k_xw1(const float* __restrict__ x,
                                             const float* __restrict__ W1) {
    __shared__ float w[128 * 10];
    int tid = threadIdx.x;
    for (int t = tid; t < 128 * 10; t += 256) w[t] = W1[t];
    __syncthreads();
    int g = blockIdx.x * 256 + tid;          // 0..32767
    int i = g >> 2, q = g & 3;               // row, quarter
    float acc[10];
#pragma unroll
    for (int k = 0; k < 10; k++) acc[k] = 0.f;
    const float4* xr = (const float4*)(x + (size_t)i * 128 + q * 32);
#pragma unroll
    for (int c4 = 0; c4 < 8; c4++) {
        float4 xv = xr[c4];
        int cb = (q * 32 + c4 * 4) * 10;
#pragma unroll
        for (int k = 0; k < 10; k++) {
            acc[k] += xv.x * w[cb + k];
            acc[k] += xv.y * w[cb + 10 + k];
            acc[k] += xv.z * w[cb + 20 + k];
            acc[k] += xv.w * w[cb + 30 + k];
        }
    }
#pragma unroll
    for (int k = 0; k < 10; k++) {
        acc[k] += __shfl_xor_sync(0xffffffffu, acc[k], 1);
        acc[k] += __shfl_xor_sync(0xffffffffu, acc[k], 2);
    }
    if (q == 0)
#pragma unroll
        for (int k = 0; k < 10; k++) g_s1T[k * NN + i] = acc[k];
}

// ---------------------------------------------------------------------------
// Main pass: U[i][k] = sum_j adj[i][j] * sT[k][j]   (+ per-row min tracking)
// 448 thr (14 warps) x 4 rows/warp = 56 rows/block, grid 147 -> ONE WAVE.
// adj streamed via cp.async.cg into per-warp 2-stage smem ring (ONE LTS pass,
// deep pipeline, zero reg cost). sT tile in smem. FFMA2 packed math.
// ---------------------------------------------------------------------------
template <int KT, int JTILE, bool TRACK, int PASS>
__global__ void __launch_bounds__(448, 1) k_pass(const float* __restrict__ adj) {
    const float* __restrict__ sT = (PASS == 1) ? g_s1T : g_s2T;
    float* __restrict__ U        = (PASS == 1) ? g_U1  : g_U2;
    extern __shared__ __align__(16) float smem[];
    float* tile = smem;                                   // KT*JTILE floats
    const int tid  = threadIdx.x;
    const int warp = tid >> 5, lane = tid & 31;
    float* abuf = smem + KT * JTILE + warp * 1024;        // 2 stages x 4 rows x 128 f
    const unsigned abase = (unsigned)__cvta_generic_to_shared(abuf);

    const int row0 = blockIdx.x * RPB + warp * 4;
    const int row0c = (row0 > NN - 4) ? (NN - 4) : row0;   // clamp: dup reads, no writes
    const bool ok = (row0 < NN);
    const float* __restrict__ rp = adj + (size_t)row0c * NN;

    unsigned long long acc[4][KT];
#pragma unroll
    for (int r = 0; r < 4; r++)
#pragma unroll
        for (int k = 0; k < KT; k++) acc[r][k] = 0ull;

    float rmin[4];
#pragma unroll
    for (int r = 0; r < 4; r++) rmin[r] = 3.4e38f;

    constexpr int NSEG = NN / 128;
    constexpr int IPT  = JTILE / 128;
    constexpr int NT   = NN / JTILE;

    // load tile 0 (L2-resident sT)
    for (int idx = tid; idx < KT * (JTILE / 4); idx += 448) {
        int k = idx / (JTILE / 4), q = idx % (JTILE / 4);
        ((float4*)tile)[idx] = ((const float4*)(sT + (size_t)k * NN))[q];
    }

    // cp.async prologue: segments 0 and 1 into stages 0/1
#pragma unroll
    for (int s = 0; s < 2; s++) {
#pragma unroll
        for (int r = 0; r < 4; r++)
            cp_async16(abase + (unsigned)((s * 512 + r * 128 + lane * 4) * 4),
                       rp + (size_t)r * NN + s * 128 + lane * 4);
        asm volatile("cp.async.commit_group;");
    }
    __syncthreads();   // tile 0 visible

    for (int tI = 0; tI < NT; tI++) {
        if (tI > 0) {
            __syncthreads();
            for (int idx = tid; idx < KT * (JTILE / 4); idx += 448) {
                int k = idx / (JTILE / 4), q = idx % (JTILE / 4);
                ((float4*)tile)[idx] =
                    ((const float4*)(sT + (size_t)k * NN + (size_t)tI * JTILE))[q];
            }
            __syncthreads();
        }
#pragma unroll 2
        for (int it = 0; it < IPT; it++) {
            const int seg = tI * IPT + it;
            asm volatile("cp.async.wait_group 1;");   // stage seg&1 ready
            // read this warp's 4 rows from smem stage (conflict-free LDS.128)
            longlong2 a[4];
#pragma unroll
            for (int r = 0; r < 4; r++)
                a[r] = *(const longlong2*)(abuf + (seg & 1) * 512 + r * 128 + lane * 4);
            // issue segment seg+2 into stage (seg+2)&1 (dummy re-read of seg 0 at end)
            {
                const int sn = seg + 2;
                const int goff = (sn < NSEG) ? sn * 128 : 0;
#pragma unroll
                for (int r = 0; r < 4; r++)
                    cp_async16(abase + (unsigned)((((sn & 1) * 512) + r * 128 + lane * 4) * 4),
                               rp + (size_t)r * NN + goff + lane * 4);
                asm volatile("cp.async.commit_group;");
            }
            if (TRACK) {
#pragma unroll
                for (int r = 0; r < 4; r++) {
                    float2 lo = u2f((unsigned long long)a[r].x);
                    float2 hi = u2f((unsigned long long)a[r].y);
                    rmin[r] = fminf(rmin[r], fminf(fminf(lo.x, lo.y), fminf(hi.x, hi.y)));
                }
            }
            const int js = it * 128 + lane * 4;
#pragma unroll
            for (int k = 0; k < KT; k++) {
                longlong2 sv = *(const longlong2*)&tile[k * JTILE + js];
#pragma unroll
                for (int r = 0; r < 4; r++) {
                    acc[r][k] = ffma2((unsigned long long)a[r].x, (unsigned long long)sv.x, acc[r][k]);
                    acc[r][k] = ffma2((unsigned long long)a[r].y, (unsigned long long)sv.y, acc[r][k]);
                }
            }
        }
    }
    asm volatile("cp.async.wait_group 0;");   // drain dummies before exit

    // lane reduction + writes
#pragma unroll
    for (int r = 0; r < 4; r++) {
#pragma unroll
        for (int k = 0; k < KT; k++) {
            float2 v = u2f(acc[r][k]);
            float s = v.x + v.y;
#pragma unroll
            for (int o = 16; o > 0; o >>= 1) s += __shfl_xor_sync(0xffffffffu, s, o);
            if (lane == 0 && ok) U[(size_t)(row0c + r) * KT + k] = s;
        }
        if (TRACK) {
            float m = rmin[r];
#pragma unroll
            for (int o = 16; o > 0; o >>= 1) m = fminf(m, __shfl_xor_sync(0xffffffffu, m, o));
            if (lane == 0 && ok) g_minrow[row0c + r] = m;
        }
    }
}

// ---------------------------------------------------------------------------
// K3: scan minrow -> dinv defaults + defect list + warp-per-defect recount
// ---------------------------------------------------------------------------
__global__ void __launch_bounds__(1024) k_scan(const float* __restrict__ adj) {
    __shared__ int warp_cnt[32];
    __shared__ int warp_off[32];
    __shared__ int base;
    int tid = threadIdx.x, w = tid >> 5, lane = tid & 31;
    if (tid == 0) base = 0;
    __syncthreads();
    for (int chunk = 0; chunk < NN; chunk += 1024) {
        int i = chunk + tid;
        bool f = (g_minrow[i] <= 0.0f);
        g_dinv[i] = DINV_C;
        unsigned m = __ballot_sync(0xffffffffu, f);
        if (lane == 0) warp_cnt[w] = __popc(m);
        __syncthreads();
        if (tid == 0) {
            int o = base;
            for (int q = 0; q < 32; q++) { warp_off[q] = o; o += warp_cnt[q]; }
            base = o;
        }
        __syncthreads();
        if (f) {
            int pos = warp_off[w] + __popc(m & ((1u << lane) - 1u));
            if (pos < MAXD) g_defect[pos] = i;
        }
        __syncthreads();
    }
    int nd = (base > MAXD) ? MAXD : base;
    if (tid == 0) g_ndef = nd;
    __syncthreads();
    // recount: one warp per defect row
    for (int d = w; d < nd; d += 32) {
        int j = g_defect[d];
        const float4* row = (const float4*)(adj + (size_t)j * NN);
        int cnt = 0;
        for (int t = lane; t < NN / 4; t += 32) {
            float4 v = row[t];
            cnt += (v.x > 0.f) + (v.y > 0.f) + (v.z > 0.f) + (v.w > 0.f);
        }
#pragma unroll
        for (int o = 16; o > 0; o >>= 1) cnt += __shfl_xor_sync(0xffffffffu, cnt, o);
        if (lane == 0)
            g_dinv[j] = (cnt > 0) ? (1.0f / sqrtf((float)cnt)) : __int_as_float(0x7f800000);
    }
}

// ---------------------------------------------------------------------------
// K5: defect correction + h = relu(gcn1) + s2T = (h@W2)*dinv (transposed)
// ---------------------------------------------------------------------------
__global__ void __launch_bounds__(128) k_h_s2(const float* __restrict__ adj,
                                              const float* __restrict__ b1,
                                              const float* __restrict__ W2) {
    __shared__ float sb1[10], sW2[50];
    __shared__ int   sjd[MAXD];
    __shared__ float sdv[MAXD];
    __shared__ float sxw[MAXD * 10];
    __shared__ int   snd;
    int tid = threadIdx.x;
    if (tid < 10) sb1[tid] = b1[tid];
    if (tid < 50) sW2[tid] = W2[tid];
    if (tid == 0) { int n = g_ndef; snd = (n > MAXD) ? MAXD : n; }
    __syncthreads();
    int nd = snd;
    for (int d = tid; d < nd; d += blockDim.x) {
        int j = g_defect[d];
        sjd[d] = j;
        sdv[d] = g_dinv[j] - DINV_C;
        for (int k = 0; k < 10; k++) sxw[d * 10 + k] = g_s1T[k * NN + j];
    }
    __syncthreads();

    int i = blockIdx.x * blockDim.x + tid;
    float di = g_dinv[i];
    float u[10];
#pragma unroll
    for (int k = 0; k < 10; k++) u[k] = DINV_C * g_U1[(size_t)i * 10 + k];
    for (int d = 0; d < nd; d++) {
        float a = adj[(size_t)i * NN + sjd[d]] * sdv[d];
#pragma unroll
        for (int k = 0; k < 10; k++) u[k] += a * sxw[d * 10 + k];
    }
    float h[10];
#pragma unroll
    for (int k = 0; k < 10; k++) {
        float self = g_s1T[k * NN + i] * di;
        float v = di * (u[k] + self) + sb1[k];
        h[k] = v > 0.f ? v : 0.f;
    }
#pragma unroll
    for (int m = 0; m < 5; m++) {
        float s = 0.f;
#pragma unroll
        for (int k = 0; k < 10; k++) s += h[k] * sW2[k * 5 + m];
        g_s2T[m * NN + i] = s * di;
    }
}

// ---------------------------------------------------------------------------
// K6a: partial column sums of dinv*(U2 + s2T) over i, 64 blocks
// ---------------------------------------------------------------------------
__global__ void __launch_bounds__(128) k_final_a() {
    __shared__ float wsum[4][5];
    int tid = threadIdx.x, lane = tid & 31, w = tid >> 5;
    int i = blockIdx.x * 128 + tid;
    float di = g_dinv[i];
    float s[5];
#pragma unroll
    for (int m = 0; m < 5; m++)
        s[m] = di * (g_U2[(size_t)i * 5 + m] + g_s2T[m * NN + i]);
#pragma unroll
    for (int m = 0; m < 5; m++) {
        float v = s[m];
#pragma unroll
        for (int o = 16; o > 0; o >>= 1) v += __shfl_xor_sync(0xffffffffu, v, o);
        if (lane == 0) wsum[w][m] = v;
    }
    __syncthreads();
    if (tid < 5) {
        float t = wsum[0][tid] + wsum[1][tid] + wsum[2][tid] + wsum[3][tid];
        g_part[blockIdx.x * 5 + tid] = t;
    }
}

// ---------------------------------------------------------------------------
// K6b: finish mean + tiny MLP head, writes 7 outputs
// ---------------------------------------------------------------------------
__global__ void __launch_bounds__(32) k_final_b(const float* __restrict__ b2,
                                                const float* __restrict__ fc1W,
                                                const float* __restrict__ fc1b,
                                                const float* __restrict__ fcW,
                                                const float* __restrict__ fcb,
                                                float* __restrict__ out, int out_size) {
    if (threadIdx.x == 0) {
        float z[5], z2[5];
        for (int m = 0; m < 5; m++) {
            float t = 0.f;
            for (int q = 0; q < 64; q++) t += g_part[q * 5 + m];
            t = t * (1.0f / (float)NN) + b2[m];
            z[m] = t > 0.f ? t : 0.f;
        }
        for (int j = 0; j < 5; j++) {
            float a = fc1b[j];
            for (int m = 0; m < 5; m++) a += z[m] * fc1W[m * 5 + j];
            z2[j] = a > 0.f ? a : 0.f;
        }
        float y[2];
        for (int t2 = 0; t2 < 2; t2++) {
            float a = fcb[t2];
            for (int j = 0; j < 5; j++) a += z2[j] * fcW[j * 2 + t2];
            y[t2] = 1.0f / (1.0f + expf(-a));
        }
        for (int m = 0; m < 5; m++) if (m < out_size) out[m] = z[m];
        if (out_size > 5) out[5] = y[0];
        if (out_size > 6) out[6] = y[1];
    }
}

// ---------------------------------------------------------------------------
extern "C" void kernel_launch(void* const* d_in, const int* in_sizes, int n_in,
                              void* d_out, int out_size) {
    const float* x    = (const float*)d_in[0];
    const float* adj  = (const float*)d_in[1];
    const float* W1   = (const float*)d_in[2];
    const float* b1   = (const float*)d_in[3];
    const float* W2   = (const float*)d_in[4];
    const float* b2   = (const float*)d_in[5];
    const float* fc1W = (const float*)d_in[6];
    const float* fc1b = (const float*)d_in[7];
    const float* fcW  = (const float*)d_in[8];
    const float* fcb  = (const float*)d_in[9];
    float* out = (float*)d_out;

    // pass1: KT=10, JTILE=4096 -> 160KB tile + 56KB adj ring = 216KB (one reload)
    // pass2: KT=5,  JTILE=8192 -> 160KB tile + 56KB adj ring = 216KB (zero reloads)
    const int smem1 = (10 * 4096 + 14 * 1024) * 4;
    const int smem2 = (5 * 8192 + 14 * 1024) * 4;
    cudaFuncSetAttribute(k_pass<10, 4096, true, 1>,
                         cudaFuncAttributeMaxDynamicSharedMemorySize, smem1);
    cudaFuncSetAttribute(k_pass<5, 8192, false, 2>,
                         cudaFuncAttributeMaxDynamicSharedMemorySize, smem2);

    k_xw1<<<128, 256>>>(x, W1);
    k_pass<10, 4096, true, 1><<<GRIDP, 448, smem1>>>(adj);
    k_scan<<<1, 1024>>>(adj);
    k_h_s2<<<64, 128>>>(adj, b1, W2);
    k_pass<5, 8192, false, 2><<<GRIDP, 448, smem2>>>(adj);
    k_final_a<<<64, 128>>>();
    k_final_b<<<1, 32>>>(b2, fc1W, fc1b, fcW, fcb, out, out_size);
}